// round 3
// baseline (speedup 1.0000x reference)
#include <cuda_runtime.h>

#define PMAX 32
#define COUT 64
#define NB1 296
#define EPSV 1e-5f

// Scratch (no allocations allowed): deterministic per-block partials + folded params.
__device__ float g_part[NB1 * 16];
__device__ float g_Wp[4 * COUT];   // [c][o] folded W' = s_o * W[o][c]
__device__ float g_bp[COUT];       // folded b' = s_o*(b_o - mu_o) + beta_o

typedef unsigned long long u64;

__device__ __forceinline__ u64 pk2(float a, float b) {
    u64 r; asm("mov.b64 %0, {%1,%2};" : "=l"(r) : "f"(a), "f"(b)); return r;
}
__device__ __forceinline__ void upk2(u64 v, float& a, float& b) {
    asm("mov.b64 {%0,%1}, %2;" : "=f"(a), "=f"(b) : "l"(v));
}
__device__ __forceinline__ u64 fma2(u64 a, u64 b, u64 c) {
    u64 d; asm("fma.rn.f32x2 %0, %1, %2, %3;" : "=l"(d) : "l"(a), "l"(b), "l"(c)); return d;
}

// ---------------------------------------------------------------------------
// Pass 1: masked reduction over all (m,p) points -> 15 scalars per block:
//   count, sum_x[4], upper-tri of sum(x x^T)[10]
// ---------------------------------------------------------------------------
__global__ void __launch_bounds__(256) pass1_kernel(
    const float* __restrict__ feat, const int* __restrict__ npts, int M)
{
    const int T = M * PMAX;
    float cnt = 0.f;
    float s0=0,s1=0,s2=0,s3=0;
    float q00=0,q01=0,q02=0,q03=0,q11=0,q12=0,q13=0,q22=0,q23=0,q33=0;

    for (int i = blockIdx.x * blockDim.x + threadIdx.x; i < T;
         i += gridDim.x * blockDim.x) {
        int m = i >> 5, p = i & 31;
        int n = __ldg(&npts[m]);
        if (p < n) {
            float4 v = __ldg(&((const float4*)feat)[i]);
            cnt += 1.f;
            s0 += v.x; s1 += v.y; s2 += v.z; s3 += v.w;
            q00 += v.x*v.x; q01 += v.x*v.y; q02 += v.x*v.z; q03 += v.x*v.w;
            q11 += v.y*v.y; q12 += v.y*v.z; q13 += v.y*v.w;
            q22 += v.z*v.z; q23 += v.z*v.w; q33 += v.w*v.w;
        }
    }

    float vals[15] = {cnt, s0,s1,s2,s3, q00,q01,q02,q03,q11,q12,q13,q22,q23,q33};
    #pragma unroll
    for (int k = 0; k < 15; k++) {
        #pragma unroll
        for (int off = 16; off > 0; off >>= 1)
            vals[k] += __shfl_down_sync(0xffffffffu, vals[k], off);
    }

    __shared__ float sh[8][16];
    int w = threadIdx.x >> 5, l = threadIdx.x & 31;
    if (l == 0) {
        #pragma unroll
        for (int k = 0; k < 15; k++) sh[w][k] = vals[k];
    }
    __syncthreads();
    if (threadIdx.x < 15) {
        float t = 0.f;
        #pragma unroll
        for (int ww = 0; ww < 8; ww++) t += sh[ww][threadIdx.x];
        g_part[blockIdx.x * 16 + threadIdx.x] = t;
    }
}

// ---------------------------------------------------------------------------
// Pass 1b (single block): reduce partials, compute mu/var analytically,
// fold BN scale into the linear layer (W', b').
// ---------------------------------------------------------------------------
__global__ void __launch_bounds__(256) pass1b_kernel(
    const float* __restrict__ W, const float* __restrict__ b,
    const float* __restrict__ gamma, const float* __restrict__ beta)
{
    __shared__ float red[16][16];
    __shared__ float fin[16];
    int t = threadIdx.x;
    int stat = t & 15, grp = t >> 4;
    float s = 0.f;
    for (int k = grp; k < NB1; k += 16) s += g_part[k * 16 + stat];
    red[grp][stat] = s;
    __syncthreads();
    if (t < 16) {
        float tt = 0.f;
        #pragma unroll
        for (int g = 0; g < 16; g++) tt += red[g][t];
        fin[t] = tt;
    }
    __syncthreads();

    if (t < COUT) {
        float N  = fmaxf(fin[0], 1.f);
        float S0 = fin[1], S1 = fin[2], S2 = fin[3], S3 = fin[4];
        float q00=fin[5], q01=fin[6], q02=fin[7], q03=fin[8];
        float q11=fin[9], q12=fin[10], q13=fin[11];
        float q22=fin[12], q23=fin[13], q33=fin[14];

        float w0 = W[t*4+0], w1 = W[t*4+1], w2 = W[t*4+2], w3 = W[t*4+3];
        float bo = b[t];
        float wS = w0*S0 + w1*S1 + w2*S2 + w3*S3;
        float mu = (wS + bo * N) / N;
        float wQw = w0*(q00*w0 + q01*w1 + q02*w2 + q03*w3)
                  + w1*(q01*w0 + q11*w1 + q12*w2 + q13*w3)
                  + w2*(q02*w0 + q12*w1 + q22*w2 + q23*w3)
                  + w3*(q03*w0 + q13*w1 + q23*w2 + q33*w3);
        float Eh2 = (wQw + 2.f*bo*wS + bo*bo*N) / N;
        float var = fmaxf(Eh2 - mu*mu, 0.f);
        float sc  = gamma[t] * rsqrtf(var + EPSV);

        g_Wp[0*COUT + t] = sc * w0;
        g_Wp[1*COUT + t] = sc * w1;
        g_Wp[2*COUT + t] = sc * w2;
        g_Wp[3*COUT + t] = sc * w3;
        g_bp[t] = sc * (bo - mu) + beta[t];
    }
}

// ---------------------------------------------------------------------------
// Pass 2: one warp per voxel. Lane l owns channels {l, l+32}.
// Points staged in SMEM pair-transposed so LDS.128 yields packed
// (x_p, x_{p+1}) f32x2 operands; inner GEMV runs on fma.rn.f32x2
// (two points per instruction).
// ---------------------------------------------------------------------------
__global__ void __launch_bounds__(256) pass2_kernel(
    const float* __restrict__ feat, const int* __restrict__ npts,
    float* __restrict__ out, int M)
{
    __shared__ __align__(16) float sp[8][PMAX * 4];  // per-warp 128 floats
    int w = threadIdx.x >> 5, l = threadIdx.x & 31;
    int m = blockIdx.x * 8 + w;

    // Folded params for this lane's two channels (o0 = l, o1 = l+32).
    float wa0 = g_Wp[0*COUT + l],      wa1 = g_Wp[1*COUT + l];
    float wa2 = g_Wp[2*COUT + l],      wa3 = g_Wp[3*COUT + l];
    float wb0 = g_Wp[0*COUT + 32 + l], wb1 = g_Wp[1*COUT + 32 + l];
    float wb2 = g_Wp[2*COUT + 32 + l], wb3 = g_Wp[3*COUT + 32 + l];
    float ba  = g_bp[l], bb = g_bp[32 + l];

    u64 WA0 = pk2(wa0, wa0), WA1 = pk2(wa1, wa1), WA2 = pk2(wa2, wa2), WA3 = pk2(wa3, wa3);
    u64 WB0 = pk2(wb0, wb0), WB1 = pk2(wb1, wb1), WB2 = pk2(wb2, wb2), WB3 = pk2(wb3, wb3);
    u64 BA  = pk2(ba, ba),   BB  = pk2(bb, bb);

    if (m >= M) return;

    int n = __ldg(&npts[m]);
    float* s = sp[w];

    // Stage only valid points: lane p -> pair-transposed layout
    // s[(p/2)*8 + c*2 + (p&1)] = x[m][p][c]
    if (l < n) {
        float4 v = __ldg(&((const float4*)feat)[m * PMAX + l]);
        int base = (l >> 1) * 8 + (l & 1);
        s[base + 0] = v.x;
        s[base + 2] = v.y;
        s[base + 4] = v.z;
        s[base + 6] = v.w;
    }
    __syncwarp();

    float acc0 = 0.f, acc1 = 0.f;
    int pairs = n >> 1;

    #pragma unroll 4
    for (int j = 0; j < pairs; j++) {
        const ulonglong2* q = reinterpret_cast<const ulonglong2*>(s + j * 8);
        ulonglong2 q0 = q[0];   // packed pairs for c=0, c=1
        ulonglong2 q1 = q[1];   // packed pairs for c=2, c=3
        u64 hA = BA, hB = BB;
        hA = fma2(WA0, q0.x, hA); hA = fma2(WA1, q0.y, hA);
        hA = fma2(WA2, q1.x, hA); hA = fma2(WA3, q1.y, hA);
        hB = fma2(WB0, q0.x, hB); hB = fma2(WB1, q0.y, hB);
        hB = fma2(WB2, q1.x, hB); hB = fma2(WB3, q1.y, hB);
        float f0, f1;
        upk2(hA, f0, f1);
        acc0 += fmaxf(f0, 0.f);
        acc0 += fmaxf(f1, 0.f);
        upk2(hB, f0, f1);
        acc1 += fmaxf(f0, 0.f);
        acc1 += fmaxf(f1, 0.f);
    }

    if (n & 1) {  // odd tail: point n-1 (even index, slot 0 of pair)
        int p = n - 1;
        const float* sb = s + (p >> 1) * 8 + (p & 1);
        float x0 = sb[0], x1 = sb[2], x2 = sb[4], x3 = sb[6];
        float hA = fmaf(wa0, x0, fmaf(wa1, x1, fmaf(wa2, x2, fmaf(wa3, x3, ba))));
        float hB = fmaf(wb0, x0, fmaf(wb1, x1, fmaf(wb2, x2, fmaf(wb3, x3, bb))));
        acc0 += fmaxf(hA, 0.f);
        acc1 += fmaxf(hB, 0.f);
    }

    float inv = 1.f / fmaxf((float)n, 1.f);
    out[m * COUT + l]      = acc0 * inv;
    out[m * COUT + 32 + l] = acc1 * inv;
}

// ---------------------------------------------------------------------------
extern "C" void kernel_launch(void* const* d_in, const int* in_sizes, int n_in,
                              void* d_out, int out_size)
{
    const float* feat  = (const float*)d_in[0];
    const int*   npts  = (const int*)d_in[1];
    const float* W     = (const float*)d_in[2];
    const float* b     = (const float*)d_in[3];
    const float* gamma = (const float*)d_in[4];
    const float* beta  = (const float*)d_in[5];
    float* out = (float*)d_out;
    int M = in_sizes[1];

    pass1_kernel<<<NB1, 256>>>(feat, npts, M);
    pass1b_kernel<<<1, 256>>>(W, b, gamma, beta);
    pass2_kernel<<<(M + 7) / 8, 256>>>(feat, npts, out, M);
}

// round 4
// speedup vs baseline: 1.1516x; 1.1516x over previous
#include <cuda_runtime.h>

#define PMAX 32
#define COUT 64
#define NB1 640
#define EPSV 1e-5f

// Scratch (no allocations allowed): deterministic per-block partials + folded params.
__device__ float g_part[NB1 * 16];
__device__ float g_Wp[4 * COUT];   // [c][o] folded W' = s_o * W[o][c]
__device__ float g_bp[COUT];       // folded b' = s_o*(b_o - mu_o) + beta_o

typedef unsigned long long u64;

__device__ __forceinline__ u64 pk2(float a, float b) {
    u64 r; asm("mov.b64 %0, {%1,%2};" : "=l"(r) : "f"(a), "f"(b)); return r;
}
__device__ __forceinline__ void upk2(u64 v, float& a, float& b) {
    asm("mov.b64 {%0,%1}, %2;" : "=f"(a), "=f"(b) : "l"(v));
}
__device__ __forceinline__ u64 fma2(u64 a, u64 b, u64 c) {
    u64 d; asm("fma.rn.f32x2 %0, %1, %2, %3;" : "=l"(d) : "l"(a), "l"(b), "l"(c)); return d;
}

// ---------------------------------------------------------------------------
// Pass 1: masked reduction over all (m,p) points -> 15 scalars per block.
// Loads are UNCONDITIONAL (streaming, no npts->feat dependency); only the
// accumulate is predicated. 4-way unrolled for MLP, 640 blocks for occupancy.
// ---------------------------------------------------------------------------
__global__ void __launch_bounds__(256) pass1_kernel(
    const float* __restrict__ feat, const int* __restrict__ npts, int M)
{
    const int T = M * PMAX;
    const int S = NB1 * 256;   // 163840 threads
    float cnt = 0.f;
    float s0=0,s1=0,s2=0,s3=0;
    float q00=0,q01=0,q02=0,q03=0,q11=0,q12=0,q13=0,q22=0,q23=0,q33=0;

    int t = blockIdx.x * 256 + threadIdx.x;
    for (int base = t; base < T; base += 4 * S) {
        float4 v[4]; int n[4]; int p[4]; bool ok[4];
        #pragma unroll
        for (int u = 0; u < 4; u++) {
            int i = base + u * S;
            ok[u] = (i < T);
            if (ok[u]) {
                v[u] = __ldg(&((const float4*)feat)[i]);
                n[u] = __ldg(&npts[i >> 5]);
                p[u] = i & 31;
            }
        }
        #pragma unroll
        for (int u = 0; u < 4; u++) {
            if (ok[u] && p[u] < n[u]) {
                float x = v[u].x, y = v[u].y, z = v[u].z, ww = v[u].w;
                cnt += 1.f;
                s0 += x; s1 += y; s2 += z; s3 += ww;
                q00 += x*x; q01 += x*y; q02 += x*z; q03 += x*ww;
                q11 += y*y; q12 += y*z; q13 += y*ww;
                q22 += z*z; q23 += z*ww; q33 += ww*ww;
            }
        }
    }

    float vals[15] = {cnt, s0,s1,s2,s3, q00,q01,q02,q03,q11,q12,q13,q22,q23,q33};
    #pragma unroll
    for (int k = 0; k < 15; k++) {
        #pragma unroll
        for (int off = 16; off > 0; off >>= 1)
            vals[k] += __shfl_down_sync(0xffffffffu, vals[k], off);
    }

    __shared__ float sh[8][16];
    int w = threadIdx.x >> 5, l = threadIdx.x & 31;
    if (l == 0) {
        #pragma unroll
        for (int k = 0; k < 15; k++) sh[w][k] = vals[k];
    }
    __syncthreads();
    if (threadIdx.x < 15) {
        float tt = 0.f;
        #pragma unroll
        for (int ww = 0; ww < 8; ww++) tt += sh[ww][threadIdx.x];
        g_part[blockIdx.x * 16 + threadIdx.x] = tt;
    }
}

// ---------------------------------------------------------------------------
// Pass 1b (single block): reduce partials, compute mu/var analytically,
// fold BN scale into the linear layer (W', b').
// ---------------------------------------------------------------------------
__global__ void __launch_bounds__(256) pass1b_kernel(
    const float* __restrict__ W, const float* __restrict__ b,
    const float* __restrict__ gamma, const float* __restrict__ beta)
{
    __shared__ float red[16][16];
    __shared__ float fin[16];
    int t = threadIdx.x;
    int stat = t & 15, grp = t >> 4;
    float s = 0.f;
    for (int k = grp; k < NB1; k += 16) s += g_part[k * 16 + stat];
    red[grp][stat] = s;
    __syncthreads();
    if (t < 16) {
        float tt = 0.f;
        #pragma unroll
        for (int g = 0; g < 16; g++) tt += red[g][t];
        fin[t] = tt;
    }
    __syncthreads();

    if (t < COUT) {
        float N  = fmaxf(fin[0], 1.f);
        float S0 = fin[1], S1 = fin[2], S2 = fin[3], S3 = fin[4];
        float q00=fin[5], q01=fin[6], q02=fin[7], q03=fin[8];
        float q11=fin[9], q12=fin[10], q13=fin[11];
        float q22=fin[12], q23=fin[13], q33=fin[14];

        float w0 = W[t*4+0], w1 = W[t*4+1], w2 = W[t*4+2], w3 = W[t*4+3];
        float bo = b[t];
        float wS = w0*S0 + w1*S1 + w2*S2 + w3*S3;
        float mu = (wS + bo * N) / N;
        float wQw = w0*(q00*w0 + q01*w1 + q02*w2 + q03*w3)
                  + w1*(q01*w0 + q11*w1 + q12*w2 + q13*w3)
                  + w2*(q02*w0 + q12*w1 + q22*w2 + q23*w3)
                  + w3*(q03*w0 + q13*w1 + q23*w2 + q33*w3);
        float Eh2 = (wQw + 2.f*bo*wS + bo*bo*N) / N;
        float var = fmaxf(Eh2 - mu*mu, 0.f);
        float sc  = gamma[t] * rsqrtf(var + EPSV);

        g_Wp[0*COUT + t] = sc * w0;
        g_Wp[1*COUT + t] = sc * w1;
        g_Wp[2*COUT + t] = sc * w2;
        g_Wp[3*COUT + t] = sc * w3;
        g_bp[t] = sc * (bo - mu) + beta[t];
    }
}

// ---------------------------------------------------------------------------
// Pass 2: one warp per voxel. Lane l owns channels {l, l+32}.
// Points staged in SMEM pair-transposed (stride-12 rows: 16B aligned,
// halves STS bank-conflict degree). Inner GEMV on fma.rn.f32x2.
// ReLU accumulated packed via relu(h) = 0.5h + 0.5|h| (|h| = 2x LOP3 on
// the ALU pipe), so accumulators never unpack inside the loop.
// ---------------------------------------------------------------------------
__global__ void __launch_bounds__(256) pass2_kernel(
    const float* __restrict__ feat, const int* __restrict__ npts,
    float* __restrict__ out, int M)
{
    __shared__ __align__(16) float sp[8][16 * 12];  // 16 pairs * 12 words per warp
    int w = threadIdx.x >> 5, l = threadIdx.x & 31;
    int m = blockIdx.x * 8 + w;
    if (m >= M) return;

    // Unconditional loads: no npts dependency in front of the feat LDG.
    int n = __ldg(&npts[m]);
    float4 v = __ldg(&((const float4*)feat)[m * PMAX + l]);
    float* s = sp[w];
    int base = (l >> 1) * 12 + (l & 1);
    s[base + 0] = v.x;
    s[base + 2] = v.y;
    s[base + 4] = v.z;
    s[base + 6] = v.w;

    // Folded params for this lane's two channels (o0 = l, o1 = l+32).
    float wa0 = g_Wp[0*COUT + l],      wa1 = g_Wp[1*COUT + l];
    float wa2 = g_Wp[2*COUT + l],      wa3 = g_Wp[3*COUT + l];
    float wb0 = g_Wp[0*COUT + 32 + l], wb1 = g_Wp[1*COUT + 32 + l];
    float wb2 = g_Wp[2*COUT + 32 + l], wb3 = g_Wp[3*COUT + 32 + l];
    float ba  = g_bp[l], bb = g_bp[32 + l];

    u64 WA0 = pk2(wa0, wa0), WA1 = pk2(wa1, wa1), WA2 = pk2(wa2, wa2), WA3 = pk2(wa3, wa3);
    u64 WB0 = pk2(wb0, wb0), WB1 = pk2(wb1, wb1), WB2 = pk2(wb2, wb2), WB3 = pk2(wb3, wb3);
    u64 BA  = pk2(ba, ba),   BB  = pk2(bb, bb);
    u64 H2  = pk2(0.5f, 0.5f);
    const u64 ABSM = 0x7FFFFFFF7FFFFFFFULL;

    __syncwarp();

    u64 ACCA = 0ULL, ACCB = 0ULL;   // packed (even-sum, odd-sum) per channel
    int pairs = n >> 1;

    #pragma unroll 4
    for (int j = 0; j < pairs; j++) {
        // Uniform address across the warp -> broadcast, conflict-free.
        const ulonglong2* q = reinterpret_cast<const ulonglong2*>(s + j * 12);
        ulonglong2 q0 = q[0];   // packed (even,odd) for c=0, c=1
        ulonglong2 q1 = q[1];   // packed (even,odd) for c=2, c=3
        u64 hA = BA, hB = BB;
        hA = fma2(WA0, q0.x, hA); hA = fma2(WA1, q0.y, hA);
        hA = fma2(WA2, q1.x, hA); hA = fma2(WA3, q1.y, hA);
        hB = fma2(WB0, q0.x, hB); hB = fma2(WB1, q0.y, hB);
        hB = fma2(WB2, q1.x, hB); hB = fma2(WB3, q1.y, hB);
        u64 aA = hA & ABSM;         // |h| packed, ALU pipe
        u64 aB = hB & ABSM;
        ACCA = fma2(H2, hA, ACCA);  // += 0.5*h
        ACCA = fma2(H2, aA, ACCA);  // += 0.5*|h|   => += relu(h)
        ACCB = fma2(H2, hB, ACCB);
        ACCB = fma2(H2, aB, ACCB);
    }

    float f0, f1;
    upk2(ACCA, f0, f1); float acc0 = f0 + f1;
    upk2(ACCB, f0, f1); float acc1 = f0 + f1;

    if (n & 1) {  // odd tail: point n-1 (even index, slot 0 of its pair row)
        int p = n - 1;
        const float* sb = s + (p >> 1) * 12;
        float x0 = sb[0], x1 = sb[2], x2 = sb[4], x3 = sb[6];
        float hA = fmaf(wa0, x0, fmaf(wa1, x1, fmaf(wa2, x2, fmaf(wa3, x3, ba))));
        float hB = fmaf(wb0, x0, fmaf(wb1, x1, fmaf(wb2, x2, fmaf(wb3, x3, bb))));
        acc0 += fmaxf(hA, 0.f);
        acc1 += fmaxf(hB, 0.f);
    }

    float inv = 1.f / fmaxf((float)n, 1.f);
    out[m * COUT + l]      = acc0 * inv;
    out[m * COUT + 32 + l] = acc1 * inv;
}

// ---------------------------------------------------------------------------
extern "C" void kernel_launch(void* const* d_in, const int* in_sizes, int n_in,
                              void* d_out, int out_size)
{
    const float* feat  = (const float*)d_in[0];
    const int*   npts  = (const int*)d_in[1];
    const float* W     = (const float*)d_in[2];
    const float* b     = (const float*)d_in[3];
    const float* gamma = (const float*)d_in[4];
    const float* beta  = (const float*)d_in[5];
    float* out = (float*)d_out;
    int M = in_sizes[1];

    pass1_kernel<<<NB1, 256>>>(feat, npts, M);
    pass1b_kernel<<<1, 256>>>(W, b, gamma, beta);
    pass2_kernel<<<(M + 7) / 8, 256>>>(feat, npts, out, M);
}